// round 8
// baseline (speedup 1.0000x reference)
#include <cuda_runtime.h>
#include <cstdint>

#define N_NODES 50000
#define F_DIM 512
#define C_DIM 64
#define O_DIM 256
#define GRID_MAX 152
#define NT 128
#define NTILES ((N_NODES + NT - 1) / NT)   // 391
#define THREADS 512
#define CH_F 64                            // features per chunk
#define NCHUNK 8                           // chunks per tile (8*64 = 512 f)

typedef unsigned long long ull;

// Scratch (static device arrays; no allocation)
__device__ float g_Mpart[GRID_MAX * C_DIM * F_DIM];
__device__ float g_cspart[GRID_MAX * C_DIM];
__device__ float g_M[C_DIM * F_DIM];
__device__ float g_cs[C_DIM];
__device__ float g_pooled[C_DIM * F_DIM];
__device__ unsigned g_bar;                 // monotonic grid barrier counter

static __device__ __forceinline__ ull pack2(float lo, float hi) {
    ull r; asm("mov.b64 %0, {%1,%2};" : "=l"(r) : "f"(lo), "f"(hi)); return r;
}
static __device__ __forceinline__ void unpack2(ull v, float& lo, float& hi) {
    asm("mov.b64 {%0,%1}, %2;" : "=f"(lo), "=f"(hi) : "l"(v));
}
static __device__ __forceinline__ ull fma2(ull a, ull b, ull c) {
    ull d; asm("fma.rn.f32x2 %0, %1, %2, %3;" : "=l"(d) : "l"(a), "l"(b), "l"(c)); return d;
}
static __device__ __forceinline__ ull add2(ull a, ull b) {
    ull d; asm("add.rn.f32x2 %0, %1, %2;" : "=l"(d) : "l"(a), "l"(b)); return d;
}
static __device__ __forceinline__ void cp16(uint32_t dst, const void* src, int sz) {
    asm volatile("cp.async.cg.shared.global [%0], [%1], 16, %2;" :: "r"(dst), "l"(src), "r"(sz));
}
static __device__ __forceinline__ void cp_commit() {
    asm volatile("cp.async.commit_group;" ::: "memory");
}
static __device__ __forceinline__ void cp_wait1() {
    asm volatile("cp.async.wait_group 1;" ::: "memory");
}
static __device__ __forceinline__ void cp_wait_all() {
    asm volatile("cp.async.wait_all;" ::: "memory");
}

// Grid-wide barrier: all CTAs resident (grid == #SMs, occ 1). Monotonic counter.
static __device__ __forceinline__ void grid_sync() {
    __syncthreads();
    __threadfence();
    if (threadIdx.x == 0) {
        unsigned old = atomicAdd(&g_bar, 1u);
        unsigned target = old - (old % gridDim.x) + gridDim.x;
        while (*(volatile unsigned*)&g_bar < target) __nanosleep(64);
        __threadfence();
    }
    __syncthreads();
}

// Stage one 64-feature chunk of a tile into swizzled smem [k4 0..15][n 0..127] float4.
static __device__ __forceinline__ void stage_chunk(
    const float* __restrict__ x, int tile, int chunk, uint32_t buf_u, int tid)
{
    const int node0 = tile * NT;
    #pragma unroll
    for (int it = 0; it < 4; ++it) {
        int j = tid + it * THREADS;            // 0..2047
        int k4 = j & 15, n = j >> 4;
        int node = node0 + n;
        int ok = node < N_NODES;
        const float* src = x + (size_t)(ok ? node : 0) * F_DIM + chunk * CH_F + k4 * 4;
        uint32_t dst = buf_u + (uint32_t)((k4 * 128 + (n ^ (k4 & 7))) * 16);
        cp16(dst, src, ok ? 16 : 0);
    }
}

__global__ __launch_bounds__(THREADS, 1) void k1_fused(
    const float* __restrict__ x, const float* __restrict__ Wp, const float* __restrict__ bp,
    const float* __restrict__ We, const float* __restrict__ be,
    const float* __restrict__ Wo, const float* __restrict__ bo,
    float* __restrict__ out)
{
    extern __shared__ float sm[];
    float*  WpS = sm;                                 // 32768 floats (Wp [512][64])
    float4* buf0 = (float4*)(sm + 32768);             // 2048 cells (32KB)
    float4* buf1 = (float4*)(sm + 32768 + 8192);      // 2048 cells (32KB)
    float4* ss4  = (float4*)(sm + 32768 + 16384);     // 128 n x 16 cquad cells (32KB)
    float*  csS  = sm + 32768 + 16384 + 8192;         // 64 floats

    const int tid = threadIdx.x;
    const uint32_t buf_u[2] = {
        (uint32_t)__cvta_generic_to_shared(buf0),
        (uint32_t)__cvta_generic_to_shared(buf1)
    };
    float4* const bufs[2] = { buf0, buf1 };

    // Stage Wp once
    {
        const float4* src = (const float4*)Wp;
        float4* dst = (float4*)WpS;
        #pragma unroll
        for (int it = 0; it < 16; ++it) dst[tid + it * THREADS] = src[tid + it * THREADS];
    }
    if (tid < 64) csS[tid] = 0.f;

    // Phase A/B ownership: 2 nodes x 8 clusters per thread
    const int coct = tid & 7,  c0 = coct * 8;
    const int ng   = tid >> 3, n0g = ng * 2;
    // Phase C ownership: 4 clusters (warp-uniform) x 2 features per thread
    const int cq4 = tid >> 5;                          // warp id = cluster quad
    const int fp  = tid & 31;                          // f-pair within chunk
    const int f4c = fp >> 1, hhc = fp & 1, swc = f4c & 7;

    ull accC[NCHUNK][2][2];                            // [chunk][f][cpair]
    #pragma unroll
    for (int m = 0; m < NCHUNK; ++m)
        #pragma unroll
        for (int a = 0; a < 2; ++a) { accC[m][a][0] = 0ull; accC[m][a][1] = 0ull; }
    ull csacc[4] = {0ull, 0ull, 0ull, 0ull};

    // Bias (8 clusters) packed
    ull bias[4];
    {
        float4 b0 = ((const float4*)bp)[coct * 2];
        float4 b1 = ((const float4*)bp)[coct * 2 + 1];
        bias[0] = pack2(b0.x, b0.y); bias[1] = pack2(b0.z, b0.w);
        bias[2] = pack2(b1.x, b1.y); bias[3] = pack2(b1.z, b1.w);
    }

    int tile = blockIdx.x;
    const int G = gridDim.x;

    // Pipeline prologue: chunk 0 of first tile in flight
    if (tile < NTILES) stage_chunk(x, tile, 0, buf_u[0], tid);
    cp_commit();

    for (; tile < NTILES; tile += G) {
        const int node0 = tile * NT;

        // Phase A accumulators (2 nodes x 4 c-pairs)
        ull accA[2][4];
        #pragma unroll
        for (int j = 0; j < 4; ++j) { accA[0][j] = bias[j]; accA[1][j] = bias[j]; }

        // ============ Phase A: 8 pipelined chunks ============
        #pragma unroll
        for (int m = 0; m < NCHUNK; ++m) {
            __syncthreads();                           // everyone done reading next buf
            // Next stage: chunk m+1 (or C's chunk 0, same data layout/parity)
            int nchunk = (m + 1) & 7;
            stage_chunk(x, tile, nchunk, buf_u[(m + 1) & 1], tid);
            cp_commit();
            cp_wait1();
            __syncthreads();                           // chunk m visible to all

            const float4* b4 = bufs[m & 1];
            #pragma unroll 4
            for (int k4 = 0; k4 < 16; ++k4) {
                float4 xv0 = b4[k4 * 128 + (n0g ^ (k4 & 7))];
                float4 xv1 = b4[k4 * 128 + ((n0g + 1) ^ (k4 & 7))];
                #pragma unroll
                for (int j = 0; j < 4; ++j) {
                    const float* wrow = WpS + (m * CH_F + k4 * 4 + j) * 64 + c0;
                    ulonglong2 wA = *(const ulonglong2*)wrow;
                    ulonglong2 wB = *(const ulonglong2*)(wrow + 4);
                    float a0 = (j == 0) ? xv0.x : (j == 1) ? xv0.y : (j == 2) ? xv0.z : xv0.w;
                    float a1 = (j == 0) ? xv1.x : (j == 1) ? xv1.y : (j == 2) ? xv1.z : xv1.w;
                    ull x0 = pack2(a0, a0), x1 = pack2(a1, a1);
                    accA[0][0] = fma2(wA.x, x0, accA[0][0]);
                    accA[0][1] = fma2(wA.y, x0, accA[0][1]);
                    accA[0][2] = fma2(wB.x, x0, accA[0][2]);
                    accA[0][3] = fma2(wB.y, x0, accA[0][3]);
                    accA[1][0] = fma2(wA.x, x1, accA[1][0]);
                    accA[1][1] = fma2(wA.y, x1, accA[1][1]);
                    accA[1][2] = fma2(wB.x, x1, accA[1][2]);
                    accA[1][3] = fma2(wB.y, x1, accA[1][3]);
                }
            }
        }

        // ============ Phase B: softmax (8-lane groups own one node's 64 c) ============
        #pragma unroll
        for (int i = 0; i < 2; ++i) {
            float l[8];
            unpack2(accA[i][0], l[0], l[1]);
            unpack2(accA[i][1], l[2], l[3]);
            unpack2(accA[i][2], l[4], l[5]);
            unpack2(accA[i][3], l[6], l[7]);
            float mx = l[0];
            #pragma unroll
            for (int j = 1; j < 8; ++j) mx = fmaxf(mx, l[j]);
            #pragma unroll
            for (int d = 1; d < 8; d <<= 1) mx = fmaxf(mx, __shfl_xor_sync(0xffffffffu, mx, d));
            float e[8], s = 0.f;
            #pragma unroll
            for (int j = 0; j < 8; ++j) { e[j] = __expf(l[j] - mx); s += e[j]; }
            #pragma unroll
            for (int d = 1; d < 8; d <<= 1) s += __shfl_xor_sync(0xffffffffu, s, d);
            float r = __frcp_rn(s);
            const int n = n0g + i;
            if (node0 + n >= N_NODES) r = 0.f;
            #pragma unroll
            for (int j = 0; j < 8; ++j) e[j] *= r;
            csacc[0] = add2(csacc[0], pack2(e[0], e[1]));
            csacc[1] = add2(csacc[1], pack2(e[2], e[3]));
            csacc[2] = add2(csacc[2], pack2(e[4], e[5]));
            csacc[3] = add2(csacc[3], pack2(e[6], e[7]));
            ss4[n * 16 + coct * 2]     = make_float4(e[0], e[1], e[2], e[3]);
            ss4[n * 16 + coct * 2 + 1] = make_float4(e[4], e[5], e[6], e[7]);
        }
        __syncthreads();                               // s visible before Phase C

        // ============ Phase C: 8 pipelined chunks, c-packed accumulators ============
        #pragma unroll
        for (int m = 0; m < NCHUNK; ++m) {
            __syncthreads();
            if (m < NCHUNK - 1) {
                stage_chunk(x, tile, m + 1, buf_u[(m + 1) & 1], tid);
            } else if (tile + G < NTILES) {
                stage_chunk(x, tile + G, 0, buf_u[0], tid);
            }
            cp_commit();
            cp_wait1();
            __syncthreads();

            const char* base = (const char*)bufs[m & 1] + f4c * 2048 + hhc * 8;
            const ulonglong2* ssp = (const ulonglong2*)ss4 + cq4;
            #pragma unroll 4
            for (int n = 0; n < NT; ++n) {
                ulonglong2 s2 = ssp[n * 16];                      // broadcast c-quad
                float2 xf = *(const float2*)(base + ((n ^ swc) * 16));
                ull x0 = pack2(xf.x, xf.x), x1 = pack2(xf.y, xf.y);
                accC[m][0][0] = fma2(s2.x, x0, accC[m][0][0]);
                accC[m][0][1] = fma2(s2.y, x0, accC[m][0][1]);
                accC[m][1][0] = fma2(s2.x, x1, accC[m][1][0]);
                accC[m][1][1] = fma2(s2.y, x1, accC[m][1][1]);
            }
        }
    }
    cp_wait_all();                                     // drain stray prefetch

    // Write per-block partial M
    {
        float* mp = g_Mpart + (size_t)blockIdx.x * (C_DIM * F_DIM);
        const int cb = cq4 * 4;
        #pragma unroll
        for (int m = 0; m < NCHUNK; ++m)
            #pragma unroll
            for (int fi = 0; fi < 2; ++fi)
                #pragma unroll
                for (int cp = 0; cp < 2; ++cp) {
                    float va, vb;
                    unpack2(accC[m][fi][cp], va, vb);
                    int f = m * CH_F + fp * 2 + fi;
                    mp[(cb + 2 * cp + 0) * F_DIM + f] = va;
                    mp[(cb + 2 * cp + 1) * F_DIM + f] = vb;
                }
    }

    // Per-block partial colsum(s)
    {
        float v[8];
        unpack2(csacc[0], v[0], v[1]);
        unpack2(csacc[1], v[2], v[3]);
        unpack2(csacc[2], v[4], v[5]);
        unpack2(csacc[3], v[6], v[7]);
        #pragma unroll
        for (int j = 0; j < 8; ++j) atomicAdd(&csS[c0 + j], v[j]);
    }
    __syncthreads();
    if (tid < 64) g_cspart[blockIdx.x * 64 + tid] = csS[tid];

    // ================= In-kernel epilogue (grid-synchronized) =================
    grid_sync();

    // Reduce partials: M (blocks 0..63, coalesced) + cs (block 64)
    {
        unsigned idx = blockIdx.x * (unsigned)THREADS + (unsigned)tid;
        if (idx < C_DIM * F_DIM) {
            float s = 0.f;
            #pragma unroll 4
            for (int b = 0; b < G; ++b) s += g_Mpart[(size_t)b * (C_DIM * F_DIM) + idx];
            g_M[idx] = s;
        }
        if (blockIdx.x == 64 && tid < C_DIM) {
            float s = 0.f;
            #pragma unroll 4
            for (int b = 0; b < G; ++b) s += g_cspart[b * C_DIM + tid];
            g_cs[tid] = s;
        }
    }

    grid_sync();

    // pooled = M @ We + cs (x) be : blocks 0..15, 4 clusters each, f = tid
    if (blockIdx.x < 16) {
        const int f = tid;
        const int cb = blockIdx.x * 4;
        const float bef = be[f];
        float a0 = g_cs[cb + 0] * bef;
        float a1 = g_cs[cb + 1] * bef;
        float a2 = g_cs[cb + 2] * bef;
        float a3 = g_cs[cb + 3] * bef;
        #pragma unroll 8
        for (int k = 0; k < F_DIM; ++k) {
            float wv = We[(size_t)k * F_DIM + f];      // coalesced
            a0 += g_M[(cb + 0) * F_DIM + k] * wv;      // broadcast
            a1 += g_M[(cb + 1) * F_DIM + k] * wv;
            a2 += g_M[(cb + 2) * F_DIM + k] * wv;
            a3 += g_M[(cb + 3) * F_DIM + k] * wv;
        }
        g_pooled[(cb + 0) * F_DIM + f] = a0;
        g_pooled[(cb + 1) * F_DIM + f] = a1;
        g_pooled[(cb + 2) * F_DIM + f] = a2;
        g_pooled[(cb + 3) * F_DIM + f] = a3;
    }

    grid_sync();

    // out = pooled @ Wo + bo : blocks 0..63 (one cluster each), k split 2 ways
    if (blockIdx.x < 64) {
        const int o = tid & 255, q = tid >> 8, c = blockIdx.x;
        float a = 0.f;
        const int kbeg = q * 256;
        #pragma unroll 8
        for (int k = kbeg; k < kbeg + 256; ++k)
            a += g_pooled[c * F_DIM + k] * Wo[(size_t)k * O_DIM + o];
        float* rsm = sm + 32768;                       // reuse buffer region
        rsm[q * 256 + o] = a;
        __syncthreads();
        if (q == 0) out[c * O_DIM + o] = rsm[o] + rsm[256 + o] + bo[o];
    }
}

extern "C" void kernel_launch(void* const* d_in, const int* in_sizes, int n_in,
                              void* d_out, int out_size) {
    const float* x  = (const float*)d_in[0];
    // d_in[1] = edge_index (int64), d_in[2] = batch (int64): unused by the output
    const float* Wp = (const float*)d_in[3];
    const float* bp = (const float*)d_in[4];
    const float* We = (const float*)d_in[5];
    const float* be = (const float*)d_in[6];
    const float* Wo = (const float*)d_in[7];
    const float* bo = (const float*)d_in[8];
    float* out = (float*)d_out;

    int dev = 0;
    cudaGetDevice(&dev);
    int smc = GRID_MAX;
    cudaDeviceGetAttribute(&smc, cudaDevAttrMultiProcessorCount, dev);
    int G = smc < GRID_MAX ? smc : GRID_MAX;

    const int SMEM1 = (32768 + 16384 + 8192 + 64) * (int)sizeof(float);  // 229632 B
    cudaFuncSetAttribute(k1_fused, cudaFuncAttributeMaxDynamicSharedMemorySize, SMEM1);

    k1_fused<<<G, THREADS, SMEM1>>>(x, Wp, bp, We, be, Wo, bo, out);
}